// round 8
// baseline (speedup 1.0000x reference)
#include <cuda_runtime.h>
#include <math.h>

#define BB 32
#define SS 400
#define TT 100
#define EE 256
#define HE 256
#define HD 512
#define VV 32000

// ---------------- scratch (device globals; no allocations) ----------------
__device__ float g_srcx[SS * BB * EE];
__device__ float g_trgx[TT * BB * EE];
__device__ float g_gif[SS * BB * 3 * HE];
__device__ float g_gib[SS * BB * 3 * HE];
__device__ float g_gidec[TT * BB * 3 * HD];
__device__ float g_enhy[BB * SS * 2 * HE];
__device__ float g_h[2][2][BB * HE];      // [dir][parity][b*HE + u]
__device__ float g_hcat[BB * 2 * HE];
__device__ float g_hdec[2][BB * HD];
__device__ float g_decout[BB * TT * HD];
__device__ float g_attm[4][BB];
__device__ float g_attl[4][BB];
__device__ float g_attc[4][BB][HD];
__device__ unsigned g_bar_cnt[4];         // 0=enc dir0, 1=enc dir1, 2=dec

// ---------------- cheap monotonic grid barrier (tid0-only polling) ----------------
__device__ __forceinline__ void bar_sync(unsigned* cnt, unsigned target) {
    __syncthreads();
    if (threadIdx.x == 0) {
        unsigned p;
        asm volatile("atom.release.gpu.global.add.u32 %0,[%1],%2;"
                     : "=r"(p) : "l"(cnt), "r"(1u) : "memory");
        if (p + 1u < target) {
            unsigned v;
            for (;;) {
                asm volatile("ld.acquire.gpu.global.u32 %0,[%1];" : "=r"(v) : "l"(cnt) : "memory");
                if (v >= target) break;
                __nanosleep(32);
            }
        }
    }
    __syncthreads();
}

// ---------------- embedding gather ----------------
__global__ void embed_kernel(const int* __restrict__ ids, const float* __restrict__ table,
                             float* __restrict__ out, int seq) {
    int i = blockIdx.x * blockDim.x + threadIdx.x;
    int E4 = EE / 4;
    int total = seq * BB * E4;
    if (i >= total) return;
    int e4 = i % E4;
    int sb = i / E4;
    int b = sb % BB;
    int s = sb / BB;
    int id = ids[b * seq + s];
    ((float4*)out)[i] = ((const float4*)table)[(size_t)id * E4 + e4];
}

// ---------------- prep ----------------
__global__ void prep_kernel() {
    int i = blockIdx.x * blockDim.x + threadIdx.x;
    if (i < 4) g_bar_cnt[i] = 0u;
    if (i < 2 * BB * HE) g_h[i / (BB * HE)][0][i % (BB * HE)] = 0.f;
}

// ---------------- tf32 -> bits ----------------
__device__ __forceinline__ unsigned f2t(float x) {
    unsigned r; asm("cvt.rna.tf32.f32 %0, %1;" : "=r"(r) : "f"(x)); return r;
}

// ---------------- tf32 tensor-core GEMM (proven R7 version) ----------------
template<int KK>
__global__ void __launch_bounds__(256) gemm_tf32(
    const float* __restrict__ A, const float* __restrict__ Bm,
    const float* __restrict__ bias, float* __restrict__ C,
    int M, int N, int ldb)
{
    constexpr int NT = KK / 16;
    __shared__ unsigned sA[3][16][136];
    __shared__ unsigned sB[3][16][72];
    int bm = blockIdx.y * 128, bn = blockIdx.x * 64;
    int tid = threadIdx.x;
    int w = tid >> 5, lane = tid & 31;
    int wm = w & 3, wn = w >> 2;
    int g = lane >> 2, tg = lane & 3;
    int arow = tid >> 1, acol = (tid & 1) * 8;
    int brow = tid >> 2, bcol = (tid & 3) * 4;
    const float* Ap = A + (size_t)(bm + arow) * KK + acol;
    const float* Bp = Bm + (size_t)(bn + brow) * ldb + bcol;

    {
        float4 a0 = *(const float4*)Ap;
        float4 a1 = *(const float4*)(Ap + 4);
        float4 b0 = *(const float4*)Bp;
        sA[0][acol + 0][arow] = f2t(a0.x); sA[0][acol + 1][arow] = f2t(a0.y);
        sA[0][acol + 2][arow] = f2t(a0.z); sA[0][acol + 3][arow] = f2t(a0.w);
        sA[0][acol + 4][arow] = f2t(a1.x); sA[0][acol + 5][arow] = f2t(a1.y);
        sA[0][acol + 6][arow] = f2t(a1.z); sA[0][acol + 7][arow] = f2t(a1.w);
        sB[0][bcol + 0][brow] = f2t(b0.x); sB[0][bcol + 1][brow] = f2t(b0.y);
        sB[0][bcol + 2][brow] = f2t(b0.z); sB[0][bcol + 3][brow] = f2t(b0.w);
    }
    float4 pa0, pa1, pb;
    if (NT > 1) {
        pa0 = *(const float4*)(Ap + 16);
        pa1 = *(const float4*)(Ap + 20);
        pb  = *(const float4*)(Bp + 16);
    }
    __syncthreads();

    float d[2][4][4];
#pragma unroll
    for (int f = 0; f < 2; f++)
#pragma unroll
        for (int j = 0; j < 4; j++)
#pragma unroll
            for (int e = 0; e < 4; e++) d[f][j][e] = 0.f;

    int mr0 = wm * 32 + g;
    int nc0 = wn * 32 + g;

#pragma unroll
    for (int i = 0; i < NT; i++) {
        const int st = i % 3;
        unsigned a[2][2][4], bf[2][4][2];
#pragma unroll
        for (int kh = 0; kh < 2; kh++) {
            int kk = kh * 8;
#pragma unroll
            for (int f = 0; f < 2; f++) {
                int mr = mr0 + f * 16;
                a[kh][f][0] = sA[st][kk + tg][mr];
                a[kh][f][1] = sA[st][kk + tg][mr + 8];
                a[kh][f][2] = sA[st][kk + tg + 4][mr];
                a[kh][f][3] = sA[st][kk + tg + 4][mr + 8];
            }
#pragma unroll
            for (int j = 0; j < 4; j++) {
                int nc = nc0 + j * 8;
                bf[kh][j][0] = sB[st][kk + tg][nc];
                bf[kh][j][1] = sB[st][kk + tg + 4][nc];
            }
        }
        if (i + 1 < NT) {
            const int ns = (i + 1) % 3;
            sA[ns][acol + 0][arow] = f2t(pa0.x); sA[ns][acol + 1][arow] = f2t(pa0.y);
            sA[ns][acol + 2][arow] = f2t(pa0.z); sA[ns][acol + 3][arow] = f2t(pa0.w);
            sA[ns][acol + 4][arow] = f2t(pa1.x); sA[ns][acol + 5][arow] = f2t(pa1.y);
            sA[ns][acol + 6][arow] = f2t(pa1.z); sA[ns][acol + 7][arow] = f2t(pa1.w);
            sB[ns][bcol + 0][brow] = f2t(pb.x);  sB[ns][bcol + 1][brow] = f2t(pb.y);
            sB[ns][bcol + 2][brow] = f2t(pb.z);  sB[ns][bcol + 3][brow] = f2t(pb.w);
        }
        if (i + 2 < NT) {
            const int k = (i + 2) * 16;
            pa0 = *(const float4*)(Ap + k);
            pa1 = *(const float4*)(Ap + k + 4);
            pb  = *(const float4*)(Bp + k);
        }
#pragma unroll
        for (int kh = 0; kh < 2; kh++)
#pragma unroll
            for (int f = 0; f < 2; f++)
#pragma unroll
                for (int j = 0; j < 4; j++)
                    asm volatile(
                        "mma.sync.aligned.m16n8k8.row.col.f32.tf32.tf32.f32 "
                        "{%0,%1,%2,%3}, {%4,%5,%6,%7}, {%8,%9}, {%0,%1,%2,%3};"
                        : "+f"(d[f][j][0]), "+f"(d[f][j][1]),
                          "+f"(d[f][j][2]), "+f"(d[f][j][3])
                        : "r"(a[kh][f][0]), "r"(a[kh][f][1]), "r"(a[kh][f][2]), "r"(a[kh][f][3]),
                          "r"(bf[kh][j][0]), "r"(bf[kh][j][1]));
        __syncthreads();
    }
#pragma unroll
    for (int f = 0; f < 2; f++) {
        int r0 = bm + wm * 32 + f * 16 + g;
#pragma unroll
        for (int j = 0; j < 4; j++) {
            int col = bn + wn * 32 + j * 8 + tg * 2;
            float b0 = __ldg(&bias[col]), b1 = __ldg(&bias[col + 1]);
            float2 v0 = make_float2(d[f][j][0] + b0, d[f][j][1] + b1);
            float2 v1 = make_float2(d[f][j][2] + b0, d[f][j][3] + b1);
            *(float2*)&C[(size_t)r0 * N + col] = v0;
            *(float2*)&C[(size_t)(r0 + 8) * N + col] = v1;
        }
    }
}

// ---------------- small fp32 GEMM (e2d only, M=32, tanh) ----------------
__global__ void __launch_bounds__(256) gemm_atb(
    const float* __restrict__ A, const float* __restrict__ Bm,
    const float* __restrict__ bias, float* __restrict__ C,
    int M, int N, int K, int ldb, int act)
{
    __shared__ float sA[16][68];
    __shared__ float sB[16][68];
    int bm = blockIdx.y * 64, bn = blockIdx.x * 64;
    int tid = threadIdx.x;
    int tm = (tid >> 4) << 2, tn = (tid & 15) << 2;
    int lr = tid >> 2, lc = (tid & 3) << 2;
    float acc[4][4] = {};
    for (int k0 = 0; k0 < K; k0 += 16) {
        float4 a4 = make_float4(0.f, 0.f, 0.f, 0.f);
        if (bm + lr < M) a4 = *(const float4*)&A[(size_t)(bm + lr) * K + k0 + lc];
        sA[lc + 0][lr] = a4.x; sA[lc + 1][lr] = a4.y; sA[lc + 2][lr] = a4.z; sA[lc + 3][lr] = a4.w;
        float4 b4 = *(const float4*)&Bm[(size_t)(bn + lr) * ldb + k0 + lc];
        sB[lc + 0][lr] = b4.x; sB[lc + 1][lr] = b4.y; sB[lc + 2][lr] = b4.z; sB[lc + 3][lr] = b4.w;
        __syncthreads();
#pragma unroll
        for (int kk = 0; kk < 16; kk++) {
            float4 av = *(const float4*)&sA[kk][tm];
            float4 bv = *(const float4*)&sB[kk][tn];
            float a[4] = {av.x, av.y, av.z, av.w};
            float b[4] = {bv.x, bv.y, bv.z, bv.w};
#pragma unroll
            for (int i = 0; i < 4; i++)
#pragma unroll
                for (int j = 0; j < 4; j++) acc[i][j] += a[i] * b[j];
        }
        __syncthreads();
    }
#pragma unroll
    for (int i = 0; i < 4; i++) {
        int row = bm + tm + i;
        if (row >= M) continue;
        float4 v;
        float* pv = &v.x;
#pragma unroll
        for (int j = 0; j < 4; j++) {
            float x = acc[i][j] + bias[bn + tn + j];
            if (act == 1) x = tanhf(x);
            pv[j] = x;
        }
        *(float4*)&C[(size_t)row * N + bn + tn] = v;
    }
}

// ---------------- persistent encoder v2: 128 CTAs x 256 thr ----------------
// CTA c: dir=c>>6, ublk=c&63 (4 units). Thread: b=tid&31, slot=tid>>5;
// unit=slot&3, khalf=slot>>2 (2-way k-split, combined via smem partials).
// h in gmem [b][u]; smem h rows [b][k] stride 260 (f4 conflict-free both ways).
__global__ void __launch_bounds__(256) enc_persist(
    const float* __restrict__ Whh_f, const float* __restrict__ Whh_b,
    const float* __restrict__ bhh_f, const float* __restrict__ bhh_b)
{
    extern __shared__ float es[];
    float* swt  = es;               // [3072] 4 units x 3 gates x 256
    float* sh   = es + 3072;        // [32][260]
    float* part = es + 11392;       // [3][4][32]
    int c = blockIdx.x;
    int dir = c >> 6;
    int ublk = c & 63;
    int tid = threadIdx.x;
    int b = tid & 31;
    int slot = tid >> 5;
    int unit = slot & 3;
    int kh = slot >> 2;
    int u = ublk * 4 + unit;
    const float* Whh = dir ? Whh_b : Whh_f;
    const float* bhh = dir ? bhh_b : bhh_f;
    const float* gibase = dir ? g_gib : g_gif;
    for (int i = tid; i < 3072; i += 256) {
        int gate = i >> 10;
        int rem = i & 1023;
        swt[i] = Whh[((size_t)gate * HE + ublk * 4 + (rem >> 8)) * HE + (rem & 255)];
    }
    float br_ = bhh[u], bz_ = bhh[HE + u], bn_ = bhh[2 * HE + u];
    const float4* wr = (const float4*)&swt[(0 * 4 + unit) * 256 + kh * 128];
    const float4* wz = (const float4*)&swt[(1 * 4 + unit) * 256 + kh * 128];
    const float4* wn = (const float4*)&swt[(2 * 4 + unit) * 256 + kh * 128];
    unsigned* cnt = &g_bar_cnt[dir];
    const float* hb = sh + b * 260 + kh * 128;

    for (int t = 0; t < SS; t++) {
        if (t > 0) bar_sync(cnt, 64u * (unsigned)t);
        // fill sh[b][k]: b fixed per warp, consecutive u per lane -> conflict-free f4
        const float* hsrc = g_h[dir][t & 1];
        for (int i4 = tid; i4 < BB * HE / 4; i4 += 256) {
            int bb = i4 >> 6, u4 = (i4 & 63) * 4;
            *(float4*)&sh[bb * 260 + u4] = __ldcg((const float4*)&hsrc[bb * 256 + u4]);
        }
        __syncthreads();
        float ar = 0.f, az = 0.f, an = 0.f;
#pragma unroll 8
        for (int k4 = 0; k4 < 32; k4++) {
            float4 h4 = *(const float4*)(hb + k4 * 4);
            float4 ww;
            ww = wr[k4]; ar += h4.x * ww.x + h4.y * ww.y + h4.z * ww.z + h4.w * ww.w;
            ww = wz[k4]; az += h4.x * ww.x + h4.y * ww.y + h4.z * ww.z + h4.w * ww.w;
            ww = wn[k4]; an += h4.x * ww.x + h4.y * ww.y + h4.z * ww.z + h4.w * ww.w;
        }
        if (kh == 1) {
            part[(0 * 4 + unit) * 32 + b] = ar;
            part[(1 * 4 + unit) * 32 + b] = az;
            part[(2 * 4 + unit) * 32 + b] = an;
        }
        __syncthreads();
        if (kh == 0) {
            ar += part[(0 * 4 + unit) * 32 + b];
            az += part[(1 * 4 + unit) * 32 + b];
            an += part[(2 * 4 + unit) * 32 + b];
            int s = dir ? (SS - 1 - t) : t;
            const float* gi = gibase + (size_t)(s * BB + b) * (3 * HE);
            float ghr = ar + br_, ghz = az + bz_, ghn = an + bn_;
            float r = 1.f / (1.f + expf(-(__ldg(&gi[u]) + ghr)));
            float z = 1.f / (1.f + expf(-(__ldg(&gi[HE + u]) + ghz)));
            float n = tanhf(__ldg(&gi[2 * HE + u]) + r * ghn);
            float hp = sh[b * 260 + u];
            float hn2 = (1.f - z) * n + z * hp;
            g_h[dir][(t + 1) & 1][b * 256 + u] = hn2;
            g_enhy[((size_t)b * SS + s) * (2 * HE) + dir * HE + u] = hn2;
        }
    }
}

// ---------------- build [hT_f, hT_b] ----------------
__global__ void hcat_kernel() {
    int i = blockIdx.x * blockDim.x + threadIdx.x;
    if (i >= BB * 2 * HE) return;
    int b = i >> 9;
    int j = i & 511;
    float v;
    if (j < HE) v = g_enhy[((size_t)b * SS + (SS - 1)) * (2 * HE) + j];
    else        v = g_enhy[((size_t)b * SS + 0) * (2 * HE) + j];
    g_hcat[i] = v;
}

// ---------------- persistent decoder v2: 128 CTAs x 512 thr, 2 barriers/step ----------------
// Phase A: flash attention partials (shh filled concurrently, pre-barrier).
// Phase G: shc filled by combining 4 partials inline (Phase R folded in), GRU dots.
__global__ void __launch_bounds__(512) dec_persist(
    const float* __restrict__ dWih, const float* __restrict__ dWhh,
    const float* __restrict__ dbhh)
{
    extern __shared__ float sm[];
    float* swd    = sm;                 // [12288]
    float* shh    = sm + 12288;         // [32][516]
    float* shc    = sm + 28800;         // [32][516]
    float* smx    = sm + 45312;         // [9*132]
    float* sm_m   = sm + 46500;         // [16]
    float* sm_l   = sm + 46516;         // [16]
    float* sm_ctx = sm + 46532;         // [16*512]  (ends 54724)

    int c = blockIdx.x;
    int tid = threadIdx.x;
    int lane = tid & 31, w = tid >> 5;
    int ab = c & 31, chunk = c >> 5, s0 = chunk * (SS / 4);
    int gb = tid & 31;
    int slot = (tid >> 5) & 3;
    int which = tid >> 7;
    int gu = c * 4 + slot;

    for (int i = tid; i < 12288; i += 512) {
        int sg = i >> 11;
        int rem = i & 2047;
        int sl = rem >> 9;
        int k = rem & 511;
        int s_ = sg / 3, g2 = sg % 3;
        int uu = c * 4 + sl;
        swd[i] = (s_ == 0) ? dWhh[((size_t)g2 * HD + uu) * HD + k]
                           : dWih[((size_t)(g2 * HD + uu)) * 768 + 256 + k];
    }
    int ws = which >> 1;
    int kb = (which & 1) * 256;
    const float4* vr = (const float4*)&swd[((ws * 3 + 0) * 4 + slot) * 512 + kb];
    const float4* vz = (const float4*)&swd[((ws * 3 + 1) * 4 + slot) * 512 + kb];
    const float4* vn = (const float4*)&swd[((ws * 3 + 2) * 4 + slot) * 512 + kb];
    float db_r = dbhh[gu], db_z = dbhh[HD + gu], db_n = dbhh[2 * HD + gu];
    unsigned* cnt = &g_bar_cnt[2];
    __syncthreads();

    for (int t = 0; t < TT; t++) {
        const float* hcur = g_hdec[t & 1];
        // ---- fill shh (needed in Phase G; overlaps Phase A) ----
        for (int i4 = tid; i4 < BB * HD / 4; i4 += 512) {
            int b2 = i4 >> 7, k = (i4 & 127) * 4;
            *(float4*)&shh[b2 * 516 + k] = __ldcg((const float4*)&hcur[i4 * 4]);
        }
        // ---------- Phase A: flash attention partials ----------
        {
            const float* hd = hcur + ab * HD;
            float4 hreg[4];
#pragma unroll
            for (int j = 0; j < 4; j++)
                hreg[j] = __ldcg((const float4*)(hd + (j * 32 + lane) * 4));
            const float* eb = g_enhy + (size_t)ab * SS * HD;
            float m = -1e30f, l = 0.f;
            float4 cacc[4];
#pragma unroll
            for (int j = 0; j < 4; j++) cacc[j] = make_float4(0.f, 0.f, 0.f, 0.f);
            for (int s = s0 + w; s < s0 + SS / 4; s += 16) {
                const float4* e4 = (const float4*)(eb + (size_t)s * HD);
                float4 ev[4];
                float acc = 0.f;
#pragma unroll
                for (int j = 0; j < 4; j++) {
                    ev[j] = __ldg(&e4[j * 32 + lane]);
                    acc += ev[j].x * hreg[j].x + ev[j].y * hreg[j].y
                         + ev[j].z * hreg[j].z + ev[j].w * hreg[j].w;
                }
#pragma unroll
                for (int o = 16; o; o >>= 1) acc += __shfl_xor_sync(0xffffffffu, acc, o);
                float mnew = fmaxf(m, acc);
                float scale = __expf(m - mnew);
                float p = __expf(acc - mnew);
                l = l * scale + p;
#pragma unroll
                for (int j = 0; j < 4; j++) {
                    cacc[j].x = cacc[j].x * scale + p * ev[j].x;
                    cacc[j].y = cacc[j].y * scale + p * ev[j].y;
                    cacc[j].z = cacc[j].z * scale + p * ev[j].z;
                    cacc[j].w = cacc[j].w * scale + p * ev[j].w;
                }
                m = mnew;
            }
            if (lane == 0) { sm_m[w] = m; sm_l[w] = l; }
#pragma unroll
            for (int j = 0; j < 4; j++)
                ((float4*)(sm_ctx + w * HD))[j * 32 + lane] = cacc[j];
            __syncthreads();
            float M = -1e30f;
#pragma unroll
            for (int q = 0; q < 16; q++) M = fmaxf(M, sm_m[q]);
            float L = 0.f, vv = 0.f;
            int e = tid;
#pragma unroll
            for (int q = 0; q < 16; q++) {
                float f_ = __expf(sm_m[q] - M);
                L += sm_l[q] * f_;
                vv += sm_ctx[q * HD + e] * f_;
            }
            g_attc[chunk][ab][e] = vv;
            if (tid == 0) { g_attm[chunk][ab] = M; g_attl[chunk][ab] = L; }
        }
        bar_sync(cnt, (unsigned)(128 * (2 * t + 1)));
        // ---------- Phase G: combine partials -> shc (tanh), then GRU ----------
        {
            for (int i4 = tid; i4 < BB * HD / 4; i4 += 512) {
                int b2 = i4 >> 7, k4 = i4 & 127;
                float m0 = __ldcg(&g_attm[0][b2]), m1 = __ldcg(&g_attm[1][b2]);
                float m2 = __ldcg(&g_attm[2][b2]), m3 = __ldcg(&g_attm[3][b2]);
                float M = fmaxf(fmaxf(m0, m1), fmaxf(m2, m3));
                float f0 = __expf(m0 - M), f1 = __expf(m1 - M);
                float f2 = __expf(m2 - M), f3 = __expf(m3 - M);
                float L = __ldcg(&g_attl[0][b2]) * f0 + __ldcg(&g_attl[1][b2]) * f1
                        + __ldcg(&g_attl[2][b2]) * f2 + __ldcg(&g_attl[3][b2]) * f3;
                float inv = 1.f / L;
                float4 v0 = __ldcg((const float4*)&g_attc[0][b2][k4 * 4]);
                float4 v1 = __ldcg((const float4*)&g_attc[1][b2][k4 * 4]);
                float4 v2 = __ldcg((const float4*)&g_attc[2][b2][k4 * 4]);
                float4 v3 = __ldcg((const float4*)&g_attc[3][b2][k4 * 4]);
                float4 o;
                o.x = tanhf((v0.x * f0 + v1.x * f1 + v2.x * f2 + v3.x * f3) * inv);
                o.y = tanhf((v0.y * f0 + v1.y * f1 + v2.y * f2 + v3.y * f3) * inv);
                o.z = tanhf((v0.z * f0 + v1.z * f1 + v2.z * f2 + v3.z * f3) * inv);
                o.w = tanhf((v0.w * f0 + v1.w * f1 + v2.w * f2 + v3.w * f3) * inv);
                *(float4*)&shc[b2 * 516 + k4 * 4] = o;
            }
            __syncthreads();
            const float* src = (ws ? shc : shh) + gb * 516 + kb;
            float ar = 0.f, az = 0.f, an = 0.f;
#pragma unroll 8
            for (int k4 = 0; k4 < 64; k4++) {
                float4 h4 = *(const float4*)(src + k4 * 4);
                float4 ww;
                ww = vr[k4]; ar += h4.x * ww.x + h4.y * ww.y + h4.z * ww.z + h4.w * ww.w;
                ww = vz[k4]; az += h4.x * ww.x + h4.y * ww.y + h4.z * ww.z + h4.w * ww.w;
                ww = vn[k4]; an += h4.x * ww.x + h4.y * ww.y + h4.z * ww.z + h4.w * ww.w;
            }
            int p = tid & 127;
            if (which != 0) {
                smx[((which - 1) * 3 + 0) * 132 + p] = ar;
                smx[((which - 1) * 3 + 1) * 132 + p] = az;
                smx[((which - 1) * 3 + 2) * 132 + p] = an;
            }
            __syncthreads();
            if (which == 0) {
                float ar2 = ar + smx[0 * 132 + p];
                float az2 = az + smx[1 * 132 + p];
                float an2 = an + smx[2 * 132 + p];
                float cr = smx[3 * 132 + p] + smx[6 * 132 + p];
                float cz = smx[4 * 132 + p] + smx[7 * 132 + p];
                float cn = smx[5 * 132 + p] + smx[8 * 132 + p];
                const float* gi = g_gidec + ((size_t)t * BB + gb) * (3 * HD);
                float ghr = ar2 + db_r, ghz = az2 + db_z, ghn = an2 + db_n;
                float r = 1.f / (1.f + expf(-(__ldg(&gi[gu]) + cr + ghr)));
                float z = 1.f / (1.f + expf(-(__ldg(&gi[HD + gu]) + cz + ghz)));
                float n = tanhf(__ldg(&gi[2 * HD + gu]) + cn + r * ghn);
                float hp = shh[gb * 516 + gu];
                float hn2 = (1.f - z) * n + z * hp;
                g_hdec[(t + 1) & 1][gb * HD + gu] = hn2;
                g_decout[((size_t)gb * TT + t) * HD + gu] = hn2;
            }
        }
        bar_sync(cnt, (unsigned)(128 * (2 * t + 2)));
    }
}

// ---------------- host ----------------
extern "C" void kernel_launch(void* const* d_in, const int* in_sizes, int n_in,
                              void* d_out, int out_size) {
    const int*   src_ids = (const int*)d_in[0];
    const int*   trg_ids = (const int*)d_in[1];
    const float* src_emb = (const float*)d_in[2];
    const float* trg_emb = (const float*)d_in[3];
    const float* eWihf   = (const float*)d_in[4];
    const float* eWhhf   = (const float*)d_in[5];
    const float* ebihf   = (const float*)d_in[6];
    const float* ebhhf   = (const float*)d_in[7];
    const float* eWihb   = (const float*)d_in[8];
    const float* eWhhb   = (const float*)d_in[9];
    const float* ebihb   = (const float*)d_in[10];
    const float* ebhhb   = (const float*)d_in[11];
    const float* e2dW    = (const float*)d_in[12];
    const float* e2db    = (const float*)d_in[13];
    const float* dWih    = (const float*)d_in[14];
    const float* dWhh    = (const float*)d_in[15];
    const float* dbih    = (const float*)d_in[16];
    const float* dbhh    = (const float*)d_in[17];
    const float* outW    = (const float*)d_in[18];
    const float* outb    = (const float*)d_in[19];
    float* out = (float*)d_out;

    const int ENC_SMEM = (3072 + 32 * 260 + 384) * (int)sizeof(float);   // 47104
    const int DEC_SMEM = 54724 * (int)sizeof(float);                     // 218896
    cudaFuncSetAttribute(enc_persist, cudaFuncAttributeMaxDynamicSharedMemorySize, ENC_SMEM);
    cudaFuncSetAttribute(dec_persist, cudaFuncAttributeMaxDynamicSharedMemorySize, DEC_SMEM);

    float *p_srcx, *p_trgx, *p_gif, *p_gib, *p_gidec, *p_hcat, *p_hdec, *p_decout;
    cudaGetSymbolAddress((void**)&p_srcx, g_srcx);
    cudaGetSymbolAddress((void**)&p_trgx, g_trgx);
    cudaGetSymbolAddress((void**)&p_gif, g_gif);
    cudaGetSymbolAddress((void**)&p_gib, g_gib);
    cudaGetSymbolAddress((void**)&p_gidec, g_gidec);
    cudaGetSymbolAddress((void**)&p_hcat, g_hcat);
    cudaGetSymbolAddress((void**)&p_hdec, g_hdec);
    cudaGetSymbolAddress((void**)&p_decout, g_decout);

    // 1) embeddings + prep
    embed_kernel<<<(SS * BB * (EE / 4) + 255) / 256, 256>>>(src_ids, src_emb, p_srcx, SS);
    embed_kernel<<<(TT * BB * (EE / 4) + 255) / 256, 256>>>(trg_ids, trg_emb, p_trgx, TT);
    prep_kernel<<<(2 * BB * HE + 255) / 256, 256>>>();

    // 2) time-parallel input-side GRU GEMMs (tf32, K=256)
    gemm_tf32<256><<<dim3(768 / 64, SS * BB / 128), 256>>>(p_srcx, eWihf, ebihf, p_gif, SS * BB, 768, 256);
    gemm_tf32<256><<<dim3(768 / 64, SS * BB / 128), 256>>>(p_srcx, eWihb, ebihb, p_gib, SS * BB, 768, 256);
    gemm_tf32<256><<<dim3(1536 / 64, TT * BB / 128), 256>>>(p_trgx, dWih, dbih, p_gidec, TT * BB, 1536, 768);

    // 3) persistent encoder scan (128 CTAs)
    enc_persist<<<128, 256, ENC_SMEM>>>(eWhhf, eWhhb, ebhhf, ebhhb);

    // 4) h0 = tanh([hT_f,hT_b] @ e2d_W.T + e2d_b)
    hcat_kernel<<<(BB * 2 * HE + 255) / 256, 256>>>();
    gemm_atb<<<dim3(512 / 64, 1), 256>>>(p_hcat, e2dW, e2db, p_hdec, BB, 512, 512, 512, 1);

    // 5) persistent decoder scan (2 barriers/step)
    dec_persist<<<128, 512, DEC_SMEM>>>(dWih, dWhh, dbhh);

    // 6) logits = dec_out @ out_W.T + out_b (tf32, K=512)
    gemm_tf32<512><<<dim3(VV / 64, BB * TT / 128), 256>>>(p_decout, outW, outb, out, BB * TT, VV, 512);
}

// round 9
// speedup vs baseline: 1.0944x; 1.0944x over previous
#include <cuda_runtime.h>
#include <math.h>

#define BB 32
#define SS 400
#define TT 100
#define EE 256
#define HE 256
#define HD 512
#define VV 32000

// ---------------- scratch (device globals; no allocations) ----------------
__device__ float g_srcx[SS * BB * EE];
__device__ float g_trgx[TT * BB * EE];
__device__ float g_gif[SS * BB * 3 * HE];
__device__ float g_gib[SS * BB * 3 * HE];
__device__ float g_gidec[TT * BB * 3 * HD];
__device__ float g_enhy[BB * SS * 2 * HE];
__device__ float g_hT[2][2][HE * BB];     // [dir][parity][u*BB + b] (transposed)
__device__ float g_hcat[BB * 2 * HE];
__device__ float g_hdec[2][BB * HD];
__device__ float g_ctx[BB * HD];
__device__ float g_decout[BB * TT * HD];
__device__ float g_attm[4][BB];
__device__ float g_attl[4][BB];
__device__ float g_attc[4][BB][HD];
__device__ unsigned g_bar_cnt[4];         // 0=enc dir0, 1=enc dir1, 2=dec

// ---------------- cheap monotonic grid barrier (tid0-only polling) ----------------
__device__ __forceinline__ void bar_sync(unsigned* cnt, unsigned target) {
    __syncthreads();
    if (threadIdx.x == 0) {
        unsigned p;
        asm volatile("atom.release.gpu.global.add.u32 %0,[%1],%2;"
                     : "=r"(p) : "l"(cnt), "r"(1u) : "memory");
        if (p + 1u < target) {
            unsigned v;
            for (;;) {
                asm volatile("ld.acquire.gpu.global.u32 %0,[%1];" : "=r"(v) : "l"(cnt) : "memory");
                if (v >= target) break;
                __nanosleep(32);
            }
        }
    }
    __syncthreads();
}

// ---------------- embedding gather ----------------
__global__ void embed_kernel(const int* __restrict__ ids, const float* __restrict__ table,
                             float* __restrict__ out, int seq) {
    int i = blockIdx.x * blockDim.x + threadIdx.x;
    int E4 = EE / 4;
    int total = seq * BB * E4;
    if (i >= total) return;
    int e4 = i % E4;
    int sb = i / E4;
    int b = sb % BB;
    int s = sb / BB;
    int id = ids[b * seq + s];
    ((float4*)out)[i] = ((const float4*)table)[(size_t)id * E4 + e4];
}

// ---------------- prep ----------------
__global__ void prep_kernel() {
    int i = blockIdx.x * blockDim.x + threadIdx.x;
    if (i < 4) g_bar_cnt[i] = 0u;
    if (i < 2 * BB * HE) g_hT[i / (BB * HE)][0][i % (BB * HE)] = 0.f;
}

// ---------------- tf32 -> bits ----------------
__device__ __forceinline__ unsigned f2t(float x) {
    unsigned r; asm("cvt.rna.tf32.f32 %0, %1;" : "=r"(r) : "f"(x)); return r;
}

// ---------------- tf32 tensor-core GEMM v5: k32 per sync, 4 stages ----------------
// C = A(M,K)*B(N,K)^T + bias. 128x64 tile, 256 thr (8 warps, warp tile 32x32).
// Each loop body consumes a PAIR of k16 tiles (stages 2j%4,(2j+1)%4), LDGs the
// next pair early, runs 32 MMAs, STSs the next pair, then one sync.
template<int KK>
__global__ void __launch_bounds__(256) gemm_tf32(
    const float* __restrict__ A, const float* __restrict__ Bm,
    const float* __restrict__ bias, float* __restrict__ C,
    int M, int N, int ldb)
{
    constexpr int NT = KK / 16;         // even
    constexpr int NP = NT / 2;          // pairs
    __shared__ unsigned sA[4][16][136];
    __shared__ unsigned sB[4][16][72];
    int bm = blockIdx.y * 128, bn = blockIdx.x * 64;
    int tid = threadIdx.x;
    int w = tid >> 5, lane = tid & 31;
    int wm = w & 3, wn = w >> 2;
    int g = lane >> 2, tg = lane & 3;
    int arow = tid >> 1, acol = (tid & 1) * 8;
    int brow = tid >> 2, bcol = (tid & 3) * 4;
    const float* Ap = A + (size_t)(bm + arow) * KK + acol;
    const float* Bp = Bm + (size_t)(bn + brow) * ldb + bcol;

    // preload tiles 0,1 -> stages 0,1
#pragma unroll
    for (int tIdx = 0; tIdx < 2; tIdx++) {
        float4 a0 = *(const float4*)(Ap + tIdx * 16);
        float4 a1 = *(const float4*)(Ap + tIdx * 16 + 4);
        float4 b0 = *(const float4*)(Bp + tIdx * 16);
        sA[tIdx][acol + 0][arow] = f2t(a0.x); sA[tIdx][acol + 1][arow] = f2t(a0.y);
        sA[tIdx][acol + 2][arow] = f2t(a0.z); sA[tIdx][acol + 3][arow] = f2t(a0.w);
        sA[tIdx][acol + 4][arow] = f2t(a1.x); sA[tIdx][acol + 5][arow] = f2t(a1.y);
        sA[tIdx][acol + 6][arow] = f2t(a1.z); sA[tIdx][acol + 7][arow] = f2t(a1.w);
        sB[tIdx][bcol + 0][brow] = f2t(b0.x); sB[tIdx][bcol + 1][brow] = f2t(b0.y);
        sB[tIdx][bcol + 2][brow] = f2t(b0.z); sB[tIdx][bcol + 3][brow] = f2t(b0.w);
    }
    __syncthreads();

    float d[2][4][4];
#pragma unroll
    for (int f = 0; f < 2; f++)
#pragma unroll
        for (int j = 0; j < 4; j++)
#pragma unroll
            for (int e = 0; e < 4; e++) d[f][j][e] = 0.f;

    int mr0 = wm * 32 + g;
    int nc0 = wn * 32 + g;

#pragma unroll
    for (int jp = 0; jp < NP; jp++) {
        // ---- LDG next pair early (latency hidden under the 32 MMAs) ----
        float4 na0[2], na1[2], nb[2];
        if (jp + 1 < NP) {
#pragma unroll
            for (int tIdx = 0; tIdx < 2; tIdx++) {
                const int k = (2 * jp + 2 + tIdx) * 16;
                na0[tIdx] = *(const float4*)(Ap + k);
                na1[tIdx] = *(const float4*)(Ap + k + 4);
                nb[tIdx]  = *(const float4*)(Bp + k);
            }
        }
        // ---- 4 k8 quarters: frag load + 8 MMAs each ----
#pragma unroll
        for (int kq = 0; kq < 4; kq++) {
            const int st = (2 * jp + (kq >> 1)) % 4;   // compile-time
            const int kk = (kq & 1) * 8;
            unsigned a[2][4], bf[4][2];
#pragma unroll
            for (int f = 0; f < 2; f++) {
                int mr = mr0 + f * 16;
                a[f][0] = sA[st][kk + tg][mr];
                a[f][1] = sA[st][kk + tg][mr + 8];
                a[f][2] = sA[st][kk + tg + 4][mr];
                a[f][3] = sA[st][kk + tg + 4][mr + 8];
            }
#pragma unroll
            for (int j = 0; j < 4; j++) {
                int nc = nc0 + j * 8;
                bf[j][0] = sB[st][kk + tg][nc];
                bf[j][1] = sB[st][kk + tg + 4][nc];
            }
#pragma unroll
            for (int f = 0; f < 2; f++)
#pragma unroll
                for (int j = 0; j < 4; j++)
                    asm volatile(
                        "mma.sync.aligned.m16n8k8.row.col.f32.tf32.tf32.f32 "
                        "{%0,%1,%2,%3}, {%4,%5,%6,%7}, {%8,%9}, {%0,%1,%2,%3};"
                        : "+f"(d[f][j][0]), "+f"(d[f][j][1]),
                          "+f"(d[f][j][2]), "+f"(d[f][j][3])
                        : "r"(a[f][0]), "r"(a[f][1]), "r"(a[f][2]), "r"(a[f][3]),
                          "r"(bf[j][0]), "r"(bf[j][1]));
        }
        // ---- STS next pair into the other stage pair ----
        if (jp + 1 < NP) {
#pragma unroll
            for (int tIdx = 0; tIdx < 2; tIdx++) {
                const int ns = (2 * jp + 2 + tIdx) % 4;
                sA[ns][acol + 0][arow] = f2t(na0[tIdx].x); sA[ns][acol + 1][arow] = f2t(na0[tIdx].y);
                sA[ns][acol + 2][arow] = f2t(na0[tIdx].z); sA[ns][acol + 3][arow] = f2t(na0[tIdx].w);
                sA[ns][acol + 4][arow] = f2t(na1[tIdx].x); sA[ns][acol + 5][arow] = f2t(na1[tIdx].y);
                sA[ns][acol + 6][arow] = f2t(na1[tIdx].z); sA[ns][acol + 7][arow] = f2t(na1[tIdx].w);
                sB[ns][bcol + 0][brow] = f2t(nb[tIdx].x);  sB[ns][bcol + 1][brow] = f2t(nb[tIdx].y);
                sB[ns][bcol + 2][brow] = f2t(nb[tIdx].z);  sB[ns][bcol + 3][brow] = f2t(nb[tIdx].w);
            }
        }
        __syncthreads();
    }
#pragma unroll
    for (int f = 0; f < 2; f++) {
        int r0 = bm + wm * 32 + f * 16 + g;
#pragma unroll
        for (int j = 0; j < 4; j++) {
            int col = bn + wn * 32 + j * 8 + tg * 2;
            float b0 = __ldg(&bias[col]), b1 = __ldg(&bias[col + 1]);
            float2 v0 = make_float2(d[f][j][0] + b0, d[f][j][1] + b1);
            float2 v1 = make_float2(d[f][j][2] + b0, d[f][j][3] + b1);
            *(float2*)&C[(size_t)r0 * N + col] = v0;
            *(float2*)&C[(size_t)(r0 + 8) * N + col] = v1;
        }
    }
}

// ---------------- small fp32 GEMM (e2d only, M=32, tanh) ----------------
__global__ void __launch_bounds__(256) gemm_atb(
    const float* __restrict__ A, const float* __restrict__ Bm,
    const float* __restrict__ bias, float* __restrict__ C,
    int M, int N, int K, int ldb, int act)
{
    __shared__ float sA[16][68];
    __shared__ float sB[16][68];
    int bm = blockIdx.y * 64, bn = blockIdx.x * 64;
    int tid = threadIdx.x;
    int tm = (tid >> 4) << 2, tn = (tid & 15) << 2;
    int lr = tid >> 2, lc = (tid & 3) << 2;
    float acc[4][4] = {};
    for (int k0 = 0; k0 < K; k0 += 16) {
        float4 a4 = make_float4(0.f, 0.f, 0.f, 0.f);
        if (bm + lr < M) a4 = *(const float4*)&A[(size_t)(bm + lr) * K + k0 + lc];
        sA[lc + 0][lr] = a4.x; sA[lc + 1][lr] = a4.y; sA[lc + 2][lr] = a4.z; sA[lc + 3][lr] = a4.w;
        float4 b4 = *(const float4*)&Bm[(size_t)(bn + lr) * ldb + k0 + lc];
        sB[lc + 0][lr] = b4.x; sB[lc + 1][lr] = b4.y; sB[lc + 2][lr] = b4.z; sB[lc + 3][lr] = b4.w;
        __syncthreads();
#pragma unroll
        for (int kk = 0; kk < 16; kk++) {
            float4 av = *(const float4*)&sA[kk][tm];
            float4 bv = *(const float4*)&sB[kk][tn];
            float a[4] = {av.x, av.y, av.z, av.w};
            float b[4] = {bv.x, bv.y, bv.z, bv.w};
#pragma unroll
            for (int i = 0; i < 4; i++)
#pragma unroll
                for (int j = 0; j < 4; j++) acc[i][j] += a[i] * b[j];
        }
        __syncthreads();
    }
#pragma unroll
    for (int i = 0; i < 4; i++) {
        int row = bm + tm + i;
        if (row >= M) continue;
        float4 v;
        float* pv = &v.x;
#pragma unroll
        for (int j = 0; j < 4; j++) {
            float x = acc[i][j] + bias[bn + tn + j];
            if (act == 1) x = tanhf(x);
            pv[j] = x;
        }
        *(float4*)&C[(size_t)row * N + bn + tn] = v;
    }
}

// ---------------- persistent encoder (proven R7 version): 64 CTAs x 256 thr ----------------
__global__ void __launch_bounds__(256) enc_persist(
    const float* __restrict__ Whh_f, const float* __restrict__ Whh_b,
    const float* __restrict__ bhh_f, const float* __restrict__ bhh_b)
{
    extern __shared__ float es[];
    float* swt = es;            // [3*8*256]
    float* sh  = es + 6144;     // [32][260]
    int c = blockIdx.x;
    int dir = c >> 5;
    int ublk = c & 31;
    int tid = threadIdx.x;
    int b = tid & 31;
    int ul = tid >> 5;
    int u = ublk * 8 + ul;
    const float* Whh = dir ? Whh_b : Whh_f;
    const float* bhh = dir ? bhh_b : bhh_f;
    const float* gibase = dir ? g_gib : g_gif;
    for (int i = tid; i < 6144; i += 256) {
        int gate = i >> 11;
        int rem = i & 2047;
        swt[i] = Whh[((size_t)gate * HE + ublk * 8 + (rem >> 8)) * HE + (rem & 255)];
    }
    float br_ = bhh[u], bz_ = bhh[HE + u], bn_ = bhh[2 * HE + u];
    const float4* wr = (const float4*)&swt[(0 * 8 + ul) * 256];
    const float4* wz = (const float4*)&swt[(1 * 8 + ul) * 256];
    const float4* wn = (const float4*)&swt[(2 * 8 + ul) * 256];
    unsigned* cnt = &g_bar_cnt[dir];
    const float* hb = sh + b * 260;

    for (int t = 0; t < SS; t++) {
        if (t > 0) bar_sync(cnt, (unsigned)(32 * t));
        const float* hsrc = g_hT[dir][t & 1];
        for (int i = tid; i < BB * HE; i += 256)
            sh[(i & 31) * 260 + (i >> 5)] = __ldcg(&hsrc[i]);
        __syncthreads();
        float ar = 0.f, az = 0.f, an = 0.f;
#pragma unroll 8
        for (int k4 = 0; k4 < 64; k4++) {
            float4 h4 = *(const float4*)(hb + k4 * 4);
            float4 ww;
            ww = wr[k4]; ar += h4.x * ww.x + h4.y * ww.y + h4.z * ww.z + h4.w * ww.w;
            ww = wz[k4]; az += h4.x * ww.x + h4.y * ww.y + h4.z * ww.z + h4.w * ww.w;
            ww = wn[k4]; an += h4.x * ww.x + h4.y * ww.y + h4.z * ww.z + h4.w * ww.w;
        }
        int s = dir ? (SS - 1 - t) : t;
        const float* gi = gibase + (size_t)(s * BB + b) * (3 * HE);
        float ghr = ar + br_, ghz = az + bz_, ghn = an + bn_;
        float r = 1.f / (1.f + expf(-(__ldg(&gi[u]) + ghr)));
        float z = 1.f / (1.f + expf(-(__ldg(&gi[HE + u]) + ghz)));
        float n = tanhf(__ldg(&gi[2 * HE + u]) + r * ghn);
        float hp = hb[u];
        float hn2 = (1.f - z) * n + z * hp;
        g_hT[dir][(t + 1) & 1][u * BB + b] = hn2;
        g_enhy[((size_t)b * SS + s) * (2 * HE) + dir * HE + u] = hn2;
        __syncthreads();
    }
}

// ---------------- build [hT_f, hT_b] ----------------
__global__ void hcat_kernel() {
    int i = blockIdx.x * blockDim.x + threadIdx.x;
    if (i >= BB * 2 * HE) return;
    int b = i >> 9;
    int j = i & 511;
    float v;
    if (j < HE) v = g_enhy[((size_t)b * SS + (SS - 1)) * (2 * HE) + j];
    else        v = g_enhy[((size_t)b * SS + 0) * (2 * HE) + j];
    g_hcat[i] = v;
}

// ---------------- persistent decoder (R7 structure, shh fill overlapped) ----------------
// 128 CTAs x 512 thr, 3 barriers/step, distributed Phase R.
// sm_ctx moved out of shh so shh can fill during Phase A.
__global__ void __launch_bounds__(512) dec_persist(
    const float* __restrict__ dWih, const float* __restrict__ dWhh,
    const float* __restrict__ dbhh)
{
    extern __shared__ float sm[];
    float* swd    = sm;                 // [12288]
    float* shh    = sm + 12288;         // [32][516]
    float* shc    = sm + 28800;         // [32][516]
    float* smx    = sm + 45312;         // [9*132]
    float* sm_m   = sm + 46500;         // [16]
    float* sm_l   = sm + 46516;         // [16]
    float* sm_ctx = sm + 46532;         // [16*512]  total 54724 floats

    int c = blockIdx.x;
    int tid = threadIdx.x;
    int lane = tid & 31, w = tid >> 5;
    int ab = c & 31, chunk = c >> 5, s0 = chunk * (SS / 4);
    int gb = tid & 31;
    int slot = (tid >> 5) & 3;
    int which = tid >> 7;
    int gu = c * 4 + slot;

    for (int i = tid; i < 12288; i += 512) {
        int sg = i >> 11;
        int rem = i & 2047;
        int sl = rem >> 9;
        int k = rem & 511;
        int s_ = sg / 3, g2 = sg % 3;
        int uu = c * 4 + sl;
        swd[i] = (s_ == 0) ? dWhh[((size_t)g2 * HD + uu) * HD + k]
                           : dWih[((size_t)(g2 * HD + uu)) * 768 + 256 + k];
    }
    int ws = which >> 1;
    int kb = (which & 1) * 256;
    const float4* vr = (const float4*)&swd[((ws * 3 + 0) * 4 + slot) * 512 + kb];
    const float4* vz = (const float4*)&swd[((ws * 3 + 1) * 4 + slot) * 512 + kb];
    const float4* vn = (const float4*)&swd[((ws * 3 + 2) * 4 + slot) * 512 + kb];
    float db_r = dbhh[gu], db_z = dbhh[HD + gu], db_n = dbhh[2 * HD + gu];
    unsigned* cnt = &g_bar_cnt[2];
    __syncthreads();

    for (int t = 0; t < TT; t++) {
        const float* hcur = g_hdec[t & 1];
        // ---- fill shh early (overlaps Phase A; separate smem region) ----
        for (int i4 = tid; i4 < BB * HD / 4; i4 += 512) {
            int b2 = i4 >> 7, k = (i4 & 127) * 4;
            *(float4*)&shh[b2 * 516 + k] = __ldcg((const float4*)&hcur[i4 * 4]);
        }
        // ---------- Phase A: flash attention partials ----------
        {
            const float* hd = hcur + ab * HD;
            float4 hreg[4];
#pragma unroll
            for (int j = 0; j < 4; j++)
                hreg[j] = __ldcg((const float4*)(hd + (j * 32 + lane) * 4));
            const float* eb = g_enhy + (size_t)ab * SS * HD;
            float m = -1e30f, l = 0.f;
            float4 cacc[4];
#pragma unroll
            for (int j = 0; j < 4; j++) cacc[j] = make_float4(0.f, 0.f, 0.f, 0.f);
            for (int s = s0 + w; s < s0 + SS / 4; s += 16) {
                const float4* e4 = (const float4*)(eb + (size_t)s * HD);
                float4 ev[4];
                float acc = 0.f;
#pragma unroll
                for (int j = 0; j < 4; j++) {
                    ev[j] = __ldg(&e4[j * 32 + lane]);
                    acc += ev[j].x * hreg[j].x + ev[j].y * hreg[j].y
                         + ev[j].z * hreg[j].z + ev[j].w * hreg[j].w;
                }
#pragma unroll
                for (int o = 16; o; o >>= 1) acc += __shfl_xor_sync(0xffffffffu, acc, o);
                float mnew = fmaxf(m, acc);
                float scale = __expf(m - mnew);
                float p = __expf(acc - mnew);
                l = l * scale + p;
#pragma unroll
                for (int j = 0; j < 4; j++) {
                    cacc[j].x = cacc[j].x * scale + p * ev[j].x;
                    cacc[j].y = cacc[j].y * scale + p * ev[j].y;
                    cacc[j].z = cacc[j].z * scale + p * ev[j].z;
                    cacc[j].w = cacc[j].w * scale + p * ev[j].w;
                }
                m = mnew;
            }
            if (lane == 0) { sm_m[w] = m; sm_l[w] = l; }
#pragma unroll
            for (int j = 0; j < 4; j++)
                ((float4*)(sm_ctx + w * HD))[j * 32 + lane] = cacc[j];
            __syncthreads();
            float M = -1e30f;
#pragma unroll
            for (int q = 0; q < 16; q++) M = fmaxf(M, sm_m[q]);
            float L = 0.f, vv = 0.f;
            int e = tid;
#pragma unroll
            for (int q = 0; q < 16; q++) {
                float f_ = __expf(sm_m[q] - M);
                L += sm_l[q] * f_;
                vv += sm_ctx[q * HD + e] * f_;
            }
            g_attc[chunk][ab][e] = vv;
            if (tid == 0) { g_attm[chunk][ab] = M; g_attl[chunk][ab] = L; }
        }
        bar_sync(cnt, (unsigned)(128 * (3 * t + 1)));
        // ---------- Phase R: distributed combine ----------
        if (tid < 128) {
            int idx = c * 128 + tid;
            int b2 = idx >> 9, e = idx & 511;
            float m0 = __ldcg(&g_attm[0][b2]), m1 = __ldcg(&g_attm[1][b2]);
            float m2 = __ldcg(&g_attm[2][b2]), m3 = __ldcg(&g_attm[3][b2]);
            float M = fmaxf(fmaxf(m0, m1), fmaxf(m2, m3));
            float f0 = __expf(m0 - M), f1 = __expf(m1 - M);
            float f2 = __expf(m2 - M), f3 = __expf(m3 - M);
            float L = __ldcg(&g_attl[0][b2]) * f0 + __ldcg(&g_attl[1][b2]) * f1
                    + __ldcg(&g_attl[2][b2]) * f2 + __ldcg(&g_attl[3][b2]) * f3;
            float v = __ldcg(&g_attc[0][b2][e]) * f0 + __ldcg(&g_attc[1][b2][e]) * f1
                    + __ldcg(&g_attc[2][b2][e]) * f2 + __ldcg(&g_attc[3][b2][e]) * f3;
            g_ctx[b2 * HD + e] = tanhf(v / L);
        }
        bar_sync(cnt, (unsigned)(128 * (3 * t + 2)));
        // ---------- Phase G: GRU step ----------
        {
            for (int i4 = tid; i4 < BB * HD / 4; i4 += 512) {
                int b2 = i4 >> 7, k = (i4 & 127) * 4;
                *(float4*)&shc[b2 * 516 + k] = __ldcg((const float4*)&g_ctx[i4 * 4]);
            }
            __syncthreads();
            const float* src = (ws ? shc : shh) + gb * 516 + kb;
            float ar = 0.f, az = 0.f, an = 0.f;
#pragma unroll 8
            for (int k4 = 0; k4 < 64; k4++) {
                float4 h4 = *(const float4*)(src + k4 * 4);
                float4 ww;
                ww = vr[k4]; ar += h4.x * ww.x + h4.y * ww.y + h4.z * ww.z + h4.w * ww.w;
                ww = vz[k4]; az += h4.x * ww.x + h4.y * ww.y + h4.z * ww.z + h4.w * ww.w;
                ww = vn[k4]; an += h4.x * ww.x + h4.y * ww.y + h4.z * ww.z + h4.w * ww.w;
            }
            int p = tid & 127;
            if (which != 0) {
                smx[((which - 1) * 3 + 0) * 132 + p] = ar;
                smx[((which - 1) * 3 + 1) * 132 + p] = az;
                smx[((which - 1) * 3 + 2) * 132 + p] = an;
            }
            __syncthreads();
            if (which == 0) {
                float ar2 = ar + smx[0 * 132 + p];
                float az2 = az + smx[1 * 132 + p];
                float an2 = an + smx[2 * 132 + p];
                float cr = smx[3 * 132 + p] + smx[6 * 132 + p];
                float cz = smx[4 * 132 + p] + smx[7 * 132 + p];
                float cn = smx[5 * 132 + p] + smx[8 * 132 + p];
                const float* gi = g_gidec + ((size_t)t * BB + gb) * (3 * HD);
                float ghr = ar2 + db_r, ghz = az2 + db_z, ghn = an2 + db_n;
                float r = 1.f / (1.f + expf(-(__ldg(&gi[gu]) + cr + ghr)));
                float z = 1.f / (1.f + expf(-(__ldg(&gi[HD + gu]) + cz + ghz)));
                float n = tanhf(__ldg(&gi[2 * HD + gu]) + cn + r * ghn);
                float hp = shh[gb * 516 + gu];
                float hn2 = (1.f - z) * n + z * hp;
                g_hdec[(t + 1) & 1][gb * HD + gu] = hn2;
                g_decout[((size_t)gb * TT + t) * HD + gu] = hn2;
            }
        }
        bar_sync(cnt, (unsigned)(128 * (3 * t + 3)));
    }
}

// ---------------- host ----------------
extern "C" void kernel_launch(void* const* d_in, const int* in_sizes, int n_in,
                              void* d_out, int out_size) {
    const int*   src_ids = (const int*)d_in[0];
    const int*   trg_ids = (const int*)d_in[1];
    const float* src_emb = (const float*)d_in[2];
    const float* trg_emb = (const float*)d_in[3];
    const float* eWihf   = (const float*)d_in[4];
    const float* eWhhf   = (const float*)d_in[5];
    const float* ebihf   = (const float*)d_in[6];
    const float* ebhhf   = (const float*)d_in[7];
    const float* eWihb   = (const float*)d_in[8];
    const float* eWhhb   = (const float*)d_in[9];
    const float* ebihb   = (const float*)d_in[10];
    const float* ebhhb   = (const float*)d_in[11];
    const float* e2dW    = (const float*)d_in[12];
    const float* e2db    = (const float*)d_in[13];
    const float* dWih    = (const float*)d_in[14];
    const float* dWhh    = (const float*)d_in[15];
    const float* dbih    = (const float*)d_in[16];
    const float* dbhh    = (const float*)d_in[17];
    const float* outW    = (const float*)d_in[18];
    const float* outb    = (const float*)d_in[19];
    float* out = (float*)d_out;

    const int ENC_SMEM = (6144 + 32 * 260) * (int)sizeof(float);   // 57856
    const int DEC_SMEM = 54724 * (int)sizeof(float);               // 218896
    cudaFuncSetAttribute(enc_persist, cudaFuncAttributeMaxDynamicSharedMemorySize, ENC_SMEM);
    cudaFuncSetAttribute(dec_persist, cudaFuncAttributeMaxDynamicSharedMemorySize, DEC_SMEM);

    float *p_srcx, *p_trgx, *p_gif, *p_gib, *p_gidec, *p_hcat, *p_hdec, *p_decout;
    cudaGetSymbolAddress((void**)&p_srcx, g_srcx);
    cudaGetSymbolAddress((void**)&p_trgx, g_trgx);
    cudaGetSymbolAddress((void**)&p_gif, g_gif);
    cudaGetSymbolAddress((void**)&p_gib, g_gib);
    cudaGetSymbolAddress((void**)&p_gidec, g_gidec);
    cudaGetSymbolAddress((void**)&p_hcat, g_hcat);
    cudaGetSymbolAddress((void**)&p_hdec, g_hdec);
    cudaGetSymbolAddress((void**)&p_decout, g_decout);

    // 1) embeddings + prep
    embed_kernel<<<(SS * BB * (EE / 4) + 255) / 256, 256>>>(src_ids, src_emb, p_srcx, SS);
    embed_kernel<<<(TT * BB * (EE / 4) + 255) / 256, 256>>>(trg_ids, trg_emb, p_trgx, TT);
    prep_kernel<<<(2 * BB * HE + 255) / 256, 256>>>();

    // 2) time-parallel input-side GRU GEMMs (tf32, K=256)
    gemm_tf32<256><<<dim3(768 / 64, SS * BB / 128), 256>>>(p_srcx, eWihf, ebihf, p_gif, SS * BB, 768, 256);
    gemm_tf32<256><<<dim3(768 / 64, SS * BB / 128), 256>>>(p_srcx, eWihb, ebihb, p_gib, SS * BB, 768, 256);
    gemm_tf32<256><<<dim3(1536 / 64, TT * BB / 128), 256>>>(p_trgx, dWih, dbih, p_gidec, TT * BB, 1536, 768);

    // 3) persistent encoder scan (R7: 64 CTAs)
    enc_persist<<<64, 256, ENC_SMEM>>>(eWhhf, eWhhb, ebhhf, ebhhb);

    // 4) h0 = tanh([hT_f,hT_b] @ e2d_W.T + e2d_b)
    hcat_kernel<<<(BB * 2 * HE + 255) / 256, 256>>>();
    gemm_atb<<<dim3(512 / 64, 1), 256>>>(p_hcat, e2dW, e2db, p_hdec, BB, 512, 512, 512, 1);

    // 5) persistent decoder scan (R7 structure, 3 barriers/step)
    dec_persist<<<128, 512, DEC_SMEM>>>(dWih, dWhh, dbhh);

    // 6) logits = dec_out @ out_W.T + out_b (tf32, K=512)
    gemm_tf32<512><<<dim3(VV / 64, BB * TT / 128), 256>>>(p_decout, outW, outb, out, BB * TT, VV, 512);
}